// round 17
// baseline (speedup 1.0000x reference)
#include <cuda_runtime.h>
#include <cuda_pipeline.h>

// PeripheralDWConv2d, fused FFT kernel, persistent CTAs (round 17):
//  - yconv uses packed fma.rn.f32x2 (FFMA2): taps processed in pairs,
//    window held as consecutive-element packs, weights pre-packed per pair
//  - rep0 conv results -> smem S-buffer; rep1 -> X plane after barrier
//  - everything else identical to round 16 (zero-pad fwd FFT, pruned inv FFT,
//    persistent CTAs, halo-once, input prefetch, cp.async weights)

#define KSZ 51
#define PP  13
#define RAD 25
#define NCH 128
#define NBIN 128
#define NPIMG 1024          // 8 batch-pairs * 128 channels
#define YDIM 64
#define SROW 115            // y-stride in float2
#define NTHR 512
#define NCTA 148
#define NKP 26              // tap pairs (52 taps, tap 51 = 0)
#define WPL (NKP * NBIN)    // 3328 float2 per weight plane

typedef unsigned long long u64;

__device__ float2 g_wf[NCH * KSZ * NBIN];     // conj spectra (scratch)
__device__ float2 g_w3[NCH * 3 * WPL];        // packed tap-pair planes per ch

// position of quantise(a) in coords [0,1,2,4,8,16,25] for a in [0,25]
__constant__ int c_qpos[26] = {0,1,2,2,3,3,3,3,4,4,4,4,4,4,4,4,
                               5,5,5,5,5,5,5,5,5,6};

__device__ __forceinline__ float2 cmulf(float2 a, float2 b) {
    return make_float2(a.x * b.x - a.y * b.y, a.x * b.y + a.y * b.x);
}
__device__ __forceinline__ float2 cmulc(float2 a, float2 b) {  // a * conj(b)
    return make_float2(a.x * b.x + a.y * b.y, a.y * b.x - a.x * b.y);
}

__device__ __forceinline__ u64 pack2f(float lo, float hi) {
    u64 r; asm("mov.b64 %0, {%1, %2};" : "=l"(r) : "f"(lo), "f"(hi)); return r;
}
__device__ __forceinline__ u64 ffma2(u64 a, u64 b, u64 c) {
    u64 d; asm("fma.rn.f32x2 %0, %1, %2, %3;" : "=l"(d) : "l"(a), "l"(b), "l"(c));
    return d;
}
__device__ __forceinline__ float2 unpack2f(u64 v) {
    float2 r; asm("mov.b64 {%0, %1}, %2;" : "=f"(r.x), "=f"(r.y) : "l"(v));
    return r;
}

// Per-thread stage twiddles tw[k] = exp(-2*pi*i*K/128), computed once.
__device__ __forceinline__ void compute_tw(float2 tw[7], int t) {
    int ks[7] = { t, t + 32, 2 * t, (t & 15) * 4, (t & 7) * 8,
                  (t & 3) * 16, (t & 1) * 32 };
#pragma unroll
    for (int i = 0; i < 7; ++i) {
        float s, c;
        sincospif(-(float)ks[i] / 64.0f, &s, &c);
        tw[i] = make_float2(c, s);
    }
}

// Forward 128-pt DIF for zero-padded input (elements 64..127 zero).
__device__ __forceinline__ void fft128_fwd_pad(float2 z[4], int t, const float2 tw[7]) {
    z[2] = cmulf(z[0], tw[0]);
    z[3] = cmulf(z[1], tw[1]);
    {   // d=32
        float2 a, b;
        a = z[0]; b = z[1];
        z[0] = make_float2(a.x + b.x, a.y + b.y);
        z[1] = cmulf(make_float2(a.x - b.x, a.y - b.y), tw[2]);
        a = z[2]; b = z[3];
        z[2] = make_float2(a.x + b.x, a.y + b.y);
        z[3] = cmulf(make_float2(a.x - b.x, a.y - b.y), tw[2]);
    }
#pragma unroll
    for (int s = 0; s < 5; ++s) {      // d = 16,8,4,2,1
        int d = 16 >> s;
        float2 w = (s < 4) ? tw[3 + s] : make_float2(1.f, 0.f);
        bool hi = (t & d) != 0;
#pragma unroll
        for (int j = 0; j < 4; ++j) {
            float ox = __shfl_xor_sync(0xffffffffu, z[j].x, d);
            float oy = __shfl_xor_sync(0xffffffffu, z[j].y, d);
            if (hi) {
                float2 df = make_float2(ox - z[j].x, oy - z[j].y);
                z[j] = (d == 1) ? df : cmulf(df, w);
            } else {
                z[j] = make_float2(z[j].x + ox, z[j].y + oy);
            }
        }
    }
}

// Inverse 128-pt DIT (unnormalized), crop-aware (see round 16).
__device__ __forceinline__ void fft128_inv_pruned(float2 z[4], int t, const float2 tw[7]) {
#pragma unroll
    for (int s = 0; s < 5; ++s) {      // d = 1,2,4,8,16
        int d = 1 << s;
        float2 w = (s > 0) ? tw[7 - s] : make_float2(1.f, 0.f);
        bool hi = (t & d) != 0;
#pragma unroll
        for (int j = 0; j < 4; ++j) {
            float ox = __shfl_xor_sync(0xffffffffu, z[j].x, d);
            float oy = __shfl_xor_sync(0xffffffffu, z[j].y, d);
            if (hi) {
                float2 vm = (d == 1) ? z[j] : cmulc(z[j], w);
                z[j] = make_float2(ox - vm.x, oy - vm.y);
            } else {
                float2 vo = (d == 1) ? make_float2(ox, oy)
                                     : cmulc(make_float2(ox, oy), w);
                z[j] = make_float2(z[j].x + vo.x, z[j].y + vo.y);
            }
        }
    }
    {   // len=64 local
        float2 u, v;
        v = cmulc(z[1], tw[2]); u = z[0];
        z[0] = make_float2(u.x + v.x, u.y + v.y);
        z[1] = make_float2(u.x - v.x, u.y - v.y);
        v = cmulc(z[3], tw[2]); u = z[2];
        z[2] = make_float2(u.x + v.x, u.y + v.y);
        z[3] = make_float2(u.x - v.x, u.y - v.y);
    }
    {   // len=128 local, pruned
        float2 v0 = cmulc(z[2], tw[0]);
        z[0] = make_float2(z[0].x + v0.x, z[0].y + v0.y);
        float2 v1 = cmulc(z[3], tw[1]);
        float sgn = (t < 7) ? 1.f : -1.f;
        z[1] = make_float2(fmaf(sgn, v1.x, z[1].x), fmaf(sgn, v1.y, z[1].y));
    }
}

// Weight spectra: expand + FFT, write conj spectrum AND packed tap-pair planes.
__global__ __launch_bounds__(256)
void fft_w_kernel(const float* __restrict__ wc, const float* __restrict__ kpe) {
    int t = threadIdx.x & 31, w = threadIdx.x >> 5;
    float2 tw[7]; compute_tw(tw, t);
    int row = blockIdx.x * 8 + w;                 // c*51+dy, < 6528
    int c  = row / KSZ;
    int dy = row - c * KSZ;

    int oi = dy - RAD; int ai = oi < 0 ? -oi : oi;
    int ii = 6 + (oi < 0 ? -c_qpos[ai] : c_qpos[ai]);
    const float* wrow = wc + c * (PP * PP) + ii * PP;
    const float* krow = kpe + dy * KSZ;

    float2 z[4];
    {   // dx = t
        int oj = t - RAD; int aj = oj < 0 ? -oj : oj;
        int jj = 6 + (oj < 0 ? -c_qpos[aj] : c_qpos[aj]);
        z[0] = make_float2(wrow[jj] + krow[t], 0.f);
    }
    {   // dx = t + 32
        int dx = t + 32;
        float v = 0.f;
        if (dx < KSZ) {
            int oj = dx - RAD; int aj = oj < 0 ? -oj : oj;
            int jj = 6 + (oj < 0 ? -c_qpos[aj] : c_qpos[aj]);
            v = wrow[jj] + krow[dx];
        }
        z[1] = make_float2(v, 0.f);
    }
    fft128_fwd_pad(z, t, tw);

    // packed tap-pair planes: [c][plane][k][bin], lane = tap parity
    int k   = dy >> 1;
    int par = dy & 1;
    float* base = (float*)(g_w3 + (size_t)c * (3 * WPL));
#pragma unroll
    for (int j = 0; j < 4; ++j) {
        int bin = t + 32 * j;
        float cr =  z[j].x;          // conj spectrum
        float ci = -z[j].y;
        int idx = k * NBIN + bin;
        base[(0 * WPL + idx) * 2 + par] =  cr;
        base[(1 * WPL + idx) * 2 + par] =  ci;
        base[(2 * WPL + idx) * 2 + par] = -ci;
        if (dy == 50) {              // tap 51 = 0 (parity 1 of k=25)
            int idx51 = 25 * NBIN + bin;
            base[(0 * WPL + idx51) * 2 + 1] = 0.f;
            base[(1 * WPL + idx51) * 2 + 1] = 0.f;
            base[(2 * WPL + idx51) * 2 + 1] = 0.f;
        }
    }
}

// Prefetch one packed image's per-thread FFT inputs (16 floats) to registers.
__device__ __forceinline__ void prefetch_img(float pf[16], const float* __restrict__ x,
                                             int pimg, int t, int w) {
    int pb = pimg >> 7, c = pimg & 127;
    const float* i0 = x + (((size_t)(2 * pb)     * NCH + c) << 12);
    const float* i1 = x + (((size_t)(2 * pb + 1) * NCH + c) << 12);
#pragma unroll
    for (int r = 0; r < 4; ++r) {
        int y = w * 4 + r;
        pf[r * 4 + 0] = i0[y * 64 + t];
        pf[r * 4 + 1] = i0[y * 64 + t + 32];
        pf[r * 4 + 2] = i1[y * 64 + t];
        pf[r * 4 + 3] = i1[y * 64 + t + 32];
    }
}

// yconv for one task (bin f, 8 consecutive y outputs), packed FFMA2.
__device__ __forceinline__ void yconv_task(
    const float2* __restrict__ xw,     // X + f*SROW + y0
    const u64* __restrict__ wr,        // (cr_2k, cr_2k+1) plane + f
    const u64* __restrict__ wi,        // (ci_2k, ci_2k+1) plane + f
    const u64* __restrict__ wni,       // (-ci_2k,-ci_2k+1) plane + f
    u64 accR[8], u64 accI[8])
{
    u64 pr[8], pi[8];
    float2 e0 = xw[0];
#pragma unroll
    for (int m = 0; m < 8; ++m) {
        float2 e1 = xw[m + 1];
        pr[m] = pack2f(e0.x, e1.x);
        pi[m] = pack2f(e0.y, e1.y);
        e0 = e1;
    }
    float2 ec = e0;                    // element 8
#pragma unroll
    for (int i = 0; i < 8; ++i) { accR[i] = 0ull; accI[i] = 0ull; }

#pragma unroll
    for (int k = 0; k < NKP; ++k) {
        const int dy = 2 * k;
        u64 a  = wr [k * NBIN];
        u64 b  = wi [k * NBIN];
        u64 ni = wni[k * NBIN];
#pragma unroll
        for (int i = 0; i < 8; ++i) {
            int sl = (dy + i) & 7;
            accR[i] = ffma2(pr[sl], a,  accR[i]);
            accR[i] = ffma2(pi[sl], ni, accR[i]);
            accI[i] = ffma2(pr[sl], b,  accI[i]);
            accI[i] = ffma2(pi[sl], a,  accI[i]);
        }
        if (k < NKP - 1) {             // load packs dy+8, dy+9 for next iter
            float2 f1 = xw[dy + 9];    // max idx 58 -> s <= 114, in-bounds
            float2 f2 = xw[dy + 10];
            pr[dy & 7]       = pack2f(ec.x, f1.x);
            pi[dy & 7]       = pack2f(ec.y, f1.y);
            pr[(dy + 1) & 7] = pack2f(f1.x, f2.x);
            pi[(dy + 1) & 7] = pack2f(f1.y, f2.y);
            ec = f2;
        }
    }
}

// Persistent fused kernel: grid = NCTA, each CTA loops images b, b+148, ...
__global__ __launch_bounds__(NTHR, 1)
void conv_persist_kernel(const float* __restrict__ x, float* __restrict__ out) {
    extern __shared__ float2 smf2[];
    float2* X    = smf2;                      // 128*SROW = 14720 f2
    float2* W3   = X + NBIN * SROW;           // 3*WPL   =  9984 f2
    float2* Sbuf = W3 + 3 * WPL;              // 32*128  =  4096 f2

    const int tid = threadIdx.x;
    const int t   = tid & 31;                 // lane
    const int w   = tid >> 5;                 // warp 0..15

    float2 tw[7]; compute_tw(tw, t);

    // one-time halo zero: s in [0,25) u [89,115)
    for (int i = tid; i < NBIN * 51; i += NTHR) {
        int f = i / 51, j = i - f * 51;
        int s = (j < 25) ? j : (64 + j);
        X[f * SROW + s] = make_float2(0.f, 0.f);
    }

    int pimg = blockIdx.x;
    float pf[16];
    if (pimg < NPIMG) prefetch_img(pf, x, pimg, t, w);

    while (pimg < NPIMG) {
        const int pb = pimg >> 7;
        const int c  = pimg & 127;

        // stage packed weights via cp.async (hidden under phase 1)
        {
            const float2* wsrc = g_w3 + (size_t)c * (3 * WPL);
            for (int i = tid; i < 3 * WPL; i += NTHR)
                __pipeline_memcpy_async(&W3[i], &wsrc[i], sizeof(float2));
            __pipeline_commit();
        }

        // phase 1: fwd FFT 4 rows per warp from prefetched regs, scatter
#pragma unroll
        for (int r = 0; r < 4; ++r) {
            int y = w * 4 + r;
            float2 z[4];
            z[0] = make_float2(pf[r * 4 + 0], pf[r * 4 + 2]);
            z[1] = make_float2(pf[r * 4 + 1], pf[r * 4 + 3]);
            fft128_fwd_pad(z, t, tw);
            int s = y + RAD;
#pragma unroll
            for (int j = 0; j < 4; ++j)
                X[(t + 32 * j) * SROW + s] = z[j];
        }
        __pipeline_wait_prior(0);
        __syncthreads();                       // X + W ready

        // phase 2: prefetch next image, then y-conv (2 reps of 8 outputs)
        const int pnext = pimg + NCTA;
        if (pnext < NPIMG) prefetch_img(pf, x, pnext, t, w);

        const int f0 = tid & 127;
        const int b0 = tid >> 7;               // 0..3
        const u64* wr  = (const u64*)W3 + f0;
        const u64* wi  = (const u64*)W3 + WPL + f0;
        const u64* wni = (const u64*)W3 + 2 * WPL + f0;

        // rep 0: y-blocks 0..3 -> Sbuf (disjoint from X, no barrier needed)
        {
            int y0 = b0 * 8;
            u64 aR[8], aI[8];
            yconv_task(X + f0 * SROW + y0, wr, wi, wni, aR, aI);
            float2* sb = Sbuf + y0 * NBIN + f0;
#pragma unroll
            for (int i = 0; i < 8; ++i) {
                float2 R = unpack2f(aR[i]);
                float2 I = unpack2f(aI[i]);
                sb[i * NBIN] = make_float2(R.x + R.y, I.x + I.y);
            }
        }
        // rep 1: y-blocks 4..7 -> X plane after the barrier
        {
            int y0 = (b0 + 4) * 8;             // 32..56
            u64 aR[8], aI[8];
            yconv_task(X + f0 * SROW + y0, wr, wi, wni, aR, aI);
            __syncthreads();                   // all X reads complete
            float2* sp = X + f0 * SROW + RAD + y0;
#pragma unroll
            for (int i = 0; i < 8; ++i) {
                float2 R = unpack2f(aR[i]);
                float2 I = unpack2f(aI[i]);
                sp[i] = make_float2(R.x + R.y, I.x + I.y);
            }
        }
        __syncthreads();                       // S visible everywhere

        // phase 4: inverse FFT 4 rows per warp, crop, unpack, write out
        float* o0 = out + (((size_t)(2 * pb)     * NCH + c) << 12);
        float* o1 = out + (((size_t)(2 * pb + 1) * NCH + c) << 12);
        const float scl = 1.0f / 128.0f;
#pragma unroll
        for (int r = 0; r < 4; ++r) {
            int y = w * 4 + r;
            float2 z[4];
            if (y < 32) {                      // uniform per warp
                const float2* S = Sbuf + y * NBIN;
#pragma unroll
                for (int j = 0; j < 4; ++j) z[j] = S[t + 32 * j];
            } else {
                int s = y + RAD;
#pragma unroll
                for (int j = 0; j < 4; ++j) z[j] = X[(t + 32 * j) * SROW + s];
            }
            fft128_inv_pruned(z, t, tw);
            float* p0 = o0 + y * 64;
            float* p1 = o1 + y * 64;
            p0[t + 25] = z[0].x * scl;
            p1[t + 25] = z[0].y * scl;
            int xo = (t < 7) ? (t + 57) : (t - 7);
            p0[xo] = z[1].x * scl;
            p1[xo] = z[1].y * scl;
        }
        __syncthreads();                       // S reads done before next image

        pimg = pnext;
    }
}

extern "C" void kernel_launch(void* const* d_in, const int* in_sizes, int n_in,
                              void* d_out, int out_size) {
    const float* x   = (const float*)d_in[0];   // 16*128*64*64
    const float* wc  = (const float*)d_in[1];   // 128*169
    const float* kpe = (const float*)d_in[2];   // 51*51
    float* out = (float*)d_out;

    fft_w_kernel<<<(NCH * KSZ) / 8, 256>>>(wc, kpe);   // 6528 rows

    const size_t msmem =
        (size_t)(NBIN * SROW + 3 * WPL + 32 * NBIN) * sizeof(float2); // 230400 B
    cudaFuncSetAttribute(conv_persist_kernel,
                         cudaFuncAttributeMaxDynamicSharedMemorySize, (int)msmem);
    conv_persist_kernel<<<NCTA, NTHR, msmem>>>(x, out);
}